// round 10
// baseline (speedup 1.0000x reference)
#include <cuda_runtime.h>
#include <cuda_fp16.h>
#include <math.h>
#include <stdint.h>

// Problem constants
#define Bb   2
#define NN_  2048
#define CC   1024
#define HH   16
#define DD   64
#define DFF_ 4096

// Scratch buffers (static device globals — allocation-free rule)
__device__ __half g_lnh[Bb * NN_ * CC];
__device__ __half g_qkvh[Bb * NN_ * 3 * CC];
__device__ __half g_aoh[Bb * NN_ * CC];
__device__ float  g_x1[Bb * NN_ * CC];
__device__ __half g_hbufh[Bb * NN_ * DFF_];
__device__ __half g_ph[(long long)Bb * HH * NN_ * NN_];  // unnormalized exp (half)
__device__ float  g_invs[Bb * HH * NN_];                 // 1/rowsum
__device__ __half g_wq[3 * CC * CC];
__device__ __half g_wp[CC * CC];
__device__ __half g_w1[DFF_ * CC];
__device__ __half g_w2[CC * DFF_];

// ---------------------------------------------------------------------------
// helpers
// ---------------------------------------------------------------------------
__device__ __forceinline__ float gelu_exact(float v) {
    return 0.5f * v * (1.0f + erff(v * 0.70710678118654752f));
}
__device__ __forceinline__ uint32_t smem_u32(const void* p) {
    uint32_t a;
    asm("{ .reg .u64 t; cvta.to.shared.u64 t, %1; cvt.u32.u64 %0, t; }"
        : "=r"(a) : "l"(p));
    return a;
}
__device__ __forceinline__ void cp16(uint32_t dst, const void* src) {
    asm volatile("cp.async.cg.shared.global [%0], [%1], 16;"
                 :: "r"(dst), "l"(src) : "memory");
}
__device__ __forceinline__ void mma_f16(float* d, const unsigned* a, const unsigned* b) {
    asm volatile(
        "mma.sync.aligned.m16n8k16.row.col.f32.f16.f16.f32 "
        "{%0,%1,%2,%3}, {%4,%5,%6,%7}, {%8,%9}, {%0,%1,%2,%3};\n"
        : "+f"(d[0]), "+f"(d[1]), "+f"(d[2]), "+f"(d[3])
        : "r"(a[0]), "r"(a[1]), "r"(a[2]), "r"(a[3]),
          "r"(b[0]), "r"(b[1]));
}
__device__ __forceinline__ void ldm_x4(unsigned& r0, unsigned& r1,
                                       unsigned& r2, unsigned& r3, uint32_t a) {
    asm volatile("ldmatrix.sync.aligned.m8n8.x4.shared.b16 {%0,%1,%2,%3}, [%4];"
                 : "=r"(r0), "=r"(r1), "=r"(r2), "=r"(r3) : "r"(a));
}

// ---------------------------------------------------------------------------
// weight convert fp32 -> half
// ---------------------------------------------------------------------------
__global__ void h_cvt(const float* __restrict__ s, __half* __restrict__ d, int n)
{
    int i = (blockIdx.x * 256 + threadIdx.x) * 4;
    if (i < n) {
        float4 v = *reinterpret_cast<const float4*>(&s[i]);
        *reinterpret_cast<__half2*>(&d[i])     = __floats2half2_rn(v.x, v.y);
        *reinterpret_cast<__half2*>(&d[i + 2]) = __floats2half2_rn(v.z, v.w);
    }
}

// ---------------------------------------------------------------------------
// LayerNorm: fp32 in, half out
// ---------------------------------------------------------------------------
__global__ void ln_kernel(const float* __restrict__ x,
                          const float* __restrict__ g,
                          const float* __restrict__ b,
                          __half* __restrict__ out)
{
    int row = blockIdx.x;
    long long base = (long long)row * CC;
    int t = threadIdx.x;

    float v[4];
    float s = 0.f, s2 = 0.f;
#pragma unroll
    for (int i = 0; i < 4; i++) {
        v[i] = x[base + t + i * 256];
        s  += v[i];
        s2 += v[i] * v[i];
    }
#pragma unroll
    for (int o = 16; o; o >>= 1) {
        s  += __shfl_xor_sync(0xffffffffu, s, o);
        s2 += __shfl_xor_sync(0xffffffffu, s2, o);
    }
    __shared__ float sh[16];
    int w = t >> 5, l = t & 31;
    if (l == 0) { sh[w] = s; sh[8 + w] = s2; }
    __syncthreads();
    if (t == 0) {
        float a = 0.f, c = 0.f;
#pragma unroll
        for (int i = 0; i < 8; i++) { a += sh[i]; c += sh[8 + i]; }
        sh[0] = a; sh[8] = c;
    }
    __syncthreads();
    float mu  = sh[0] * (1.0f / CC);
    float var = sh[8] * (1.0f / CC) - mu * mu;
    float inv = rsqrtf(var + 1e-5f);
#pragma unroll
    for (int i = 0; i < 4; i++) {
        int c = t + i * 256;
        out[base + c] = __float2half((v[i] - mu) * inv * g[c] + b[c]);
    }
}

// ---------------------------------------------------------------------------
// gemm_h: NT fp16 GEMM, cp.async double-buffer + ldmatrix fragments.
// A [M,K] half, B [Nc,K] half (both K-major). CTA 128x128, BK=32,
// 8 warps (2Mx4N), warp 64x32.
// Epilogue modes: normal (bias/gelu/res, fp32 or half out) or
// expmask (emask != null): out half = mask[c] ? exp2(v*ESCALE) : 0.
// ---------------------------------------------------------------------------
#define ESCALE 0.18033688f   /* 0.125 * log2(e) */

__global__ __launch_bounds__(256, 2)
void gemm_h(const __half* __restrict__ A, const __half* __restrict__ Bm,
            void* __restrict__ Cv,
            int K, int lda, int ldb, int ldc,
            long long Abs, long long Ahs,
            long long Bbs, long long Bhs,
            long long Cbs, long long Chs, int Hh,
            const float* __restrict__ bias,
            const float* __restrict__ res, int act, int outHalf,
            const int* __restrict__ emask)
{
    constexpr int LD = 40;
    constexpr int ROWB = LD * 2;
    constexpr int ASTG_B = 128 * ROWB;
    constexpr int STG_B = 2 * ASTG_B;
    __shared__ __half smh[2 * 256 * LD];

    int zb = blockIdx.z / Hh, zh = blockIdx.z % Hh;
    A  += zb * Abs + zh * Ahs;
    Bm += zb * Bbs + zh * Bhs;

    int t = threadIdx.x, w = t >> 5, lane = t & 31;
    int gid = lane >> 2, tig = lane & 3;
    int m0 = blockIdx.y * 128, n0 = blockIdx.x * 128;
    int wm = (w & 1) * 64, wn = (w >> 1) * 32;

    uint32_t sbase = smem_u32(smh);

    int frow = t >> 1;
    int fch  = (t & 1) * 2;

    auto fill = [&](int p, int k0) {
        uint32_t as = sbase + p * STG_B;
        uint32_t bs = as + ASTG_B;
#pragma unroll
        for (int c = 0; c < 2; c++) {
            int ch = fch + c;
            cp16(as + frow * ROWB + ch * 16,
                 &A[(long long)(m0 + frow) * lda + k0 + ch * 8]);
            cp16(bs + frow * ROWB + ch * 16,
                 &Bm[(long long)(n0 + frow) * ldb + k0 + ch * 8]);
        }
        asm volatile("cp.async.commit_group;" ::: "memory");
    };

    float acc[4][4][4] = {};

    fill(0, 0);
    int S = K / 32;
    for (int s = 0; s < S; s++) {
        int p = s & 1;
        if (s + 1 < S) {
            fill(p ^ 1, (s + 1) * 32);
            asm volatile("cp.async.wait_group 1;" ::: "memory");
        } else {
            asm volatile("cp.async.wait_group 0;" ::: "memory");
        }
        __syncthreads();

        uint32_t as = sbase + p * STG_B;
        uint32_t bs = as + ASTG_B;
#pragma unroll
        for (int kk = 0; kk < 32; kk += 16) {
            unsigned af[4][4], bf[4][2];
            int arow_l = (lane & 15);
            int akoff = kk + ((lane >> 4) << 3);
#pragma unroll
            for (int i = 0; i < 4; i++) {
                uint32_t addr = as + (wm + i * 16 + arow_l) * ROWB + akoff * 2;
                ldm_x4(af[i][0], af[i][1], af[i][2], af[i][3], addr);
            }
            int bj = (lane >> 4) & 1;
            int bkoff = kk + (((lane >> 3) & 1) << 3);
            int brow_l = lane & 7;
#pragma unroll
            for (int jp = 0; jp < 2; jp++) {
                uint32_t addr = bs + (wn + (jp * 2 + bj) * 8 + brow_l) * ROWB + bkoff * 2;
                ldm_x4(bf[jp * 2][0], bf[jp * 2][1],
                       bf[jp * 2 + 1][0], bf[jp * 2 + 1][1], addr);
            }
#pragma unroll
            for (int i = 0; i < 4; i++)
#pragma unroll
                for (int j = 0; j < 4; j++)
                    mma_f16(acc[i][j], af[i], bf[j]);
        }
        __syncthreads();
    }

    // epilogue
    float* Cf = (float*)Cv;
    __half* Ch = (__half*)Cv;
    long long coff = zb * Cbs + zh * Chs;
    const int* mrow = emask ? (emask + (long long)zb * NN_) : nullptr;
#pragma unroll
    for (int i = 0; i < 4; i++) {
        int r1 = m0 + wm + i * 16 + gid;
        int r2 = r1 + 8;
#pragma unroll
        for (int j = 0; j < 4; j++) {
            int c = n0 + wn + j * 8 + 2 * tig;
            float v0 = acc[i][j][0], v1 = acc[i][j][1];
            float v2 = acc[i][j][2], v3 = acc[i][j][3];
            long long i1 = coff + (long long)r1 * ldc + c;
            long long i2 = coff + (long long)r2 * ldc + c;
            if (mrow) {
                bool m0b = mrow[c] != 0, m1b = mrow[c + 1] != 0;
                v0 = m0b ? exp2f(v0 * ESCALE) : 0.f;
                v1 = m1b ? exp2f(v1 * ESCALE) : 0.f;
                v2 = m0b ? exp2f(v2 * ESCALE) : 0.f;
                v3 = m1b ? exp2f(v3 * ESCALE) : 0.f;
                *reinterpret_cast<__half2*>(&Ch[i1]) = __floats2half2_rn(v0, v1);
                *reinterpret_cast<__half2*>(&Ch[i2]) = __floats2half2_rn(v2, v3);
                continue;
            }
            if (bias) {
                float b0 = bias[c], b1 = bias[c + 1];
                v0 += b0; v1 += b1; v2 += b0; v3 += b1;
            }
            if (act) {
                v0 = gelu_exact(v0); v1 = gelu_exact(v1);
                v2 = gelu_exact(v2); v3 = gelu_exact(v3);
            }
            if (res) {
                float2 ra = *reinterpret_cast<const float2*>(&res[(long long)r1 * ldc + c]);
                float2 rb = *reinterpret_cast<const float2*>(&res[(long long)r2 * ldc + c]);
                v0 += ra.x; v1 += ra.y; v2 += rb.x; v3 += rb.y;
            }
            if (outHalf) {
                *reinterpret_cast<__half2*>(&Ch[i1]) = __floats2half2_rn(v0, v1);
                *reinterpret_cast<__half2*>(&Ch[i2]) = __floats2half2_rn(v2, v3);
            } else {
                float2 o1 = {v0, v1}, o2 = {v2, v3};
                *reinterpret_cast<float2*>(&Cf[i1]) = o1;
                *reinterpret_cast<float2*>(&Cf[i2]) = o2;
            }
        }
    }
}

// ---------------------------------------------------------------------------
// invs_kernel: one block per row. Reads unnormalized half u, computes
// invS[row] = 1/sum(u). Deterministic tree reduction.
// ---------------------------------------------------------------------------
__global__ void invs_kernel(const __half* __restrict__ u,
                            float* __restrict__ invS)
{
    long long row = blockIdx.x;
    const __half* ru = u + row * NN_;
    int t = threadIdx.x;

    uint4 raw = *reinterpret_cast<const uint4*>(&ru[t * 8]);
    const __half2* h2 = reinterpret_cast<const __half2*>(&raw);
    float s = 0.f;
#pragma unroll
    for (int i = 0; i < 4; i++) {
        float2 f = __half22float2(h2[i]);
        s += f.x + f.y;
    }
#pragma unroll
    for (int o = 16; o; o >>= 1)
        s += __shfl_xor_sync(0xffffffffu, s, o);

    __shared__ float sh[8];
    int w = t >> 5, l = t & 31;
    if (l == 0) sh[w] = s;
    __syncthreads();
    if (t == 0) {
        float tot = sh[0];
#pragma unroll
        for (int i = 1; i < 8; i++) tot += sh[i];
        invS[row] = 1.0f / tot;
    }
}

// ---------------------------------------------------------------------------
// gemm_avh: AV fp16 GEMM on UNNORMALIZED u, scaled by invS in epilogue.
// FUSED: while streaming u tiles, also writes normalized fp32 attn
// (u * invS[row]) to the attn output — replaces the old norm pass.
// A [N,N] half, V rows=k cols=d half (transposed into smem). CTA 128x64.
// ---------------------------------------------------------------------------
__global__ __launch_bounds__(256, 2)
void gemm_avh(const __half* __restrict__ A, const __half* __restrict__ V,
              __half* __restrict__ C,
              const float* __restrict__ invS,
              float* __restrict__ attn_out,
              int K, int lda, int ldb, int ldc,
              long long Abs, long long Ahs,
              long long Bbs, long long Bhs,
              long long Cbs, long long Chs, int Hh)
{
    constexpr int LD = 40;
    constexpr int ROWB = LD * 2;
    __shared__ __half As[128 * LD];
    __shared__ __half Bs[64 * LD];

    int zb = blockIdx.z / Hh, zh = blockIdx.z % Hh;
    A += zb * Abs + zh * Ahs;
    V += zb * Bbs + zh * Bhs;
    C += zb * Cbs + zh * Chs;
    invS += (long long)(zb * Hh + zh) * NN_;
    attn_out += (long long)(zb * Hh + zh) * NN_ * NN_;

    int t = threadIdx.x, w = t >> 5, lane = t & 31;
    int gid = lane >> 2, tig = lane & 3;
    int m0 = blockIdx.y * 128;
    int wm = (w & 3) * 32, wn = (w >> 2) * 32;

    int lrow = t >> 2;          // 0..63
    int lcol = (t & 3) * 8;
    int vmr = t >> 3;
    int vdc = (t & 7) * 8;

    // invS for the two rows this thread streams
    float is0 = invS[m0 + lrow];
    float is1 = invS[m0 + lrow + 64];

    uint32_t asb = smem_u32(As);
    uint32_t bsb = smem_u32(Bs);

    float acc[2][4][4] = {};

    for (int k0 = 0; k0 < K; k0 += 32) {
#pragma unroll
        for (int i = 0; i < 2; i++) {
            int r = lrow + 64 * i;
            uint4 u4 = *reinterpret_cast<const uint4*>(&A[(long long)(m0 + r) * lda + k0 + lcol]);
            *reinterpret_cast<uint4*>(&As[r * LD + lcol]) = u4;
            // fused normalized attn write (fp32)
            float isr = i ? is1 : is0;
            const __half2* h2 = reinterpret_cast<const __half2*>(&u4);
            float2 f0 = __half22float2(h2[0]);
            float2 f1 = __half22float2(h2[1]);
            float2 f2 = __half22float2(h2[2]);
            float2 f3 = __half22float2(h2[3]);
            float4 o1 = {f0.x * isr, f0.y * isr, f1.x * isr, f1.y * isr};
            float4 o2 = {f2.x * isr, f2.y * isr, f3.x * isr, f3.y * isr};
            long long ab = (long long)(m0 + r) * NN_ + k0 + lcol;
            *reinterpret_cast<float4*>(&attn_out[ab])     = o1;
            *reinterpret_cast<float4*>(&attn_out[ab + 4]) = o2;
        }
        {
            uint4 u = *reinterpret_cast<const uint4*>(&V[(long long)(k0 + vmr) * ldb + vdc]);
            const __half* hv = reinterpret_cast<const __half*>(&u);
#pragma unroll
            for (int j = 0; j < 8; j++)
                Bs[(vdc + j) * LD + vmr] = hv[j];
        }
        __syncthreads();

#pragma unroll
        for (int kk = 0; kk < 32; kk += 16) {
            unsigned af[2][4], bf[4][2];
            int arow_l = (lane & 15);
            int akoff = kk + ((lane >> 4) << 3);
#pragma unroll
            for (int i = 0; i < 2; i++) {
                uint32_t addr = asb + (wm + i * 16 + arow_l) * ROWB + akoff * 2;
                ldm_x4(af[i][0], af[i][1], af[i][2], af[i][3], addr);
            }
            int bj = (lane >> 4) & 1;
            int bkoff = kk + (((lane >> 3) & 1) << 3);
            int brow_l = lane & 7;
#pragma unroll
            for (int jp = 0; jp < 2; jp++) {
                uint32_t addr = bsb + (wn + (jp * 2 + bj) * 8 + brow_l) * ROWB + bkoff * 2;
                ldm_x4(bf[jp * 2][0], bf[jp * 2][1],
                       bf[jp * 2 + 1][0], bf[jp * 2 + 1][1], addr);
            }
#pragma unroll
            for (int i = 0; i < 2; i++)
#pragma unroll
                for (int j = 0; j < 4; j++)
                    mma_f16(acc[i][j], af[i], bf[j]);
        }
        __syncthreads();
    }

#pragma unroll
    for (int i = 0; i < 2; i++) {
        int r1 = m0 + wm + i * 16 + gid;
        int r2 = r1 + 8;
        float s1 = invS[r1], s2 = invS[r2];
#pragma unroll
        for (int j = 0; j < 4; j++) {
            int c = wn + j * 8 + 2 * tig;
            *reinterpret_cast<__half2*>(&C[(long long)r1 * ldc + c]) =
                __floats2half2_rn(acc[i][j][0] * s1, acc[i][j][1] * s1);
            *reinterpret_cast<__half2*>(&C[(long long)r2 * ldc + c]) =
                __floats2half2_rn(acc[i][j][2] * s2, acc[i][j][3] * s2);
        }
    }
}

// ---------------------------------------------------------------------------
// Launch
// ---------------------------------------------------------------------------
extern "C" void kernel_launch(void* const* d_in, const int* in_sizes, int n_in,
                              void* d_out, int out_size)
{
    const float* x      = (const float*)d_in[0];
    const int*   mask   = (const int*)  d_in[1];
    const float* qkv_w  = (const float*)d_in[2];
    const float* proj_w = (const float*)d_in[3];
    const float* proj_b = (const float*)d_in[4];
    const float* ln1_g  = (const float*)d_in[5];
    const float* ln1_b  = (const float*)d_in[6];
    const float* ln2_g  = (const float*)d_in[7];
    const float* ln2_b  = (const float*)d_in[8];
    const float* fc1_w  = (const float*)d_in[9];
    const float* fc1_b  = (const float*)d_in[10];
    const float* fc2_w  = (const float*)d_in[11];
    const float* fc2_b  = (const float*)d_in[12];

    float* out_x    = (float*)d_out;
    float* out_attn = out_x + (long long)Bb * NN_ * CC;

    __half *p_ln, *p_qkv, *p_ao, *p_h, *p_ph, *p_wq, *p_wp, *p_w1, *p_w2;
    float *p_x1, *p_invs;
    cudaGetSymbolAddress((void**)&p_ln,  g_lnh);
    cudaGetSymbolAddress((void**)&p_qkv, g_qkvh);
    cudaGetSymbolAddress((void**)&p_ao,  g_aoh);
    cudaGetSymbolAddress((void**)&p_x1,  g_x1);
    cudaGetSymbolAddress((void**)&p_h,   g_hbufh);
    cudaGetSymbolAddress((void**)&p_ph,  g_ph);
    cudaGetSymbolAddress((void**)&p_invs, g_invs);
    cudaGetSymbolAddress((void**)&p_wq,  g_wq);
    cudaGetSymbolAddress((void**)&p_wp,  g_wp);
    cudaGetSymbolAddress((void**)&p_w1,  g_w1);
    cudaGetSymbolAddress((void**)&p_w2,  g_w2);

    const int M  = Bb * NN_;                 // 4096
    const long long ZERO = 0;
    const long long NC3 = (long long)NN_ * 3 * CC;

    // 0) weights -> half
    h_cvt<<<3 * CC * CC / 1024, 256>>>(qkv_w,  p_wq, 3 * CC * CC);
    h_cvt<<<CC * CC / 1024,     256>>>(proj_w, p_wp, CC * CC);
    h_cvt<<<DFF_ * CC / 1024,   256>>>(fc1_w,  p_w1, DFF_ * CC);
    h_cvt<<<CC * DFF_ / 1024,   256>>>(fc2_w,  p_w2, CC * DFF_);

    // 1) LN1 -> half
    ln_kernel<<<M, 256>>>(x, ln1_g, ln1_b, p_ln);

    // 2) QKV
    {
        dim3 grid(3 * CC / 128, M / 128, 1);
        gemm_h<<<grid, 256>>>(p_ln, p_wq, p_qkv,
            CC, CC, CC, 3 * CC,
            ZERO, ZERO, ZERO, ZERO, ZERO, ZERO, 1,
            nullptr, nullptr, 0, 1, nullptr);
    }

    // 3) QK^T per head -> g_ph = half(exp(masked scaled logits)), unnormalized
    {
        dim3 grid(NN_ / 128, NN_ / 128, Bb * HH);
        gemm_h<<<grid, 256>>>(p_qkv, p_qkv + CC, p_ph,
            DD, 3 * CC, 3 * CC, NN_,
            NC3, DD, NC3, DD,
            (long long)HH * NN_ * NN_, (long long)NN_ * NN_, HH,
            nullptr, nullptr, 0, 1, mask);
    }

    // 4) row sums -> invS
    invs_kernel<<<Bb * HH * NN_, 256>>>(p_ph, p_invs);

    // 5) AV per head on unnormalized u (scaled by invS) + fused attn write
    {
        dim3 grid(1, NN_ / 128, Bb * HH);
        gemm_avh<<<grid, 256>>>(p_ph, p_qkv + 2 * CC, p_ao, p_invs, out_attn,
            NN_, NN_, 3 * CC, CC,
            (long long)HH * NN_ * NN_, (long long)NN_ * NN_,
            NC3, DD,
            (long long)NN_ * CC, DD, HH);
    }

    // 6) proj + residual -> x1 (fp32)
    {
        dim3 grid(CC / 128, M / 128, 1);
        gemm_h<<<grid, 256>>>(p_ao, p_wp, p_x1,
            CC, CC, CC, CC,
            ZERO, ZERO, ZERO, ZERO, ZERO, ZERO, 1,
            proj_b, x, 0, 0, nullptr);
    }

    // 7) LN2 -> half
    ln_kernel<<<M, 256>>>(p_x1, ln2_g, ln2_b, p_ln);

    // 8) FC1 + GELU -> half
    {
        dim3 grid(DFF_ / 128, M / 128, 1);
        gemm_h<<<grid, 256>>>(p_ln, p_w1, p_h,
            CC, CC, CC, DFF_,
            ZERO, ZERO, ZERO, ZERO, ZERO, ZERO, 1,
            fc1_b, nullptr, 1, 1, nullptr);
    }

    // 9) FC2 + residual -> out_x (fp32)
    {
        dim3 grid(CC / 128, M / 128, 1);
        gemm_h<<<grid, 256>>>(p_h, p_w2, out_x,
            DFF_, DFF_, DFF_, CC,
            ZERO, ZERO, ZERO, ZERO, ZERO, ZERO, 1,
            fc2_b, p_x1, 0, 0, nullptr);
    }
}

// round 11
// speedup vs baseline: 1.1075x; 1.1075x over previous
#include <cuda_runtime.h>
#include <cuda_fp16.h>
#include <math.h>
#include <stdint.h>

// Problem constants
#define Bb   2
#define NN_  2048
#define CC   1024
#define HH   16
#define DD   64
#define DFF_ 4096

// Scratch buffers (static device globals — allocation-free rule)
__device__ __half g_lnh[Bb * NN_ * CC];
__device__ __half g_qkvh[Bb * NN_ * 3 * CC];
__device__ __half g_aoh[Bb * NN_ * CC];
__device__ float  g_x1[Bb * NN_ * CC];
__device__ __half g_hbufh[Bb * NN_ * DFF_];
__device__ __half g_ph[(long long)Bb * HH * NN_ * NN_];  // unnormalized exp (half)
__device__ float  g_rowsum[Bb * HH * NN_];               // fp32 row sums (atomic)
__device__ __half g_wq[3 * CC * CC];
__device__ __half g_wp[CC * CC];
__device__ __half g_w1[DFF_ * CC];
__device__ __half g_w2[CC * DFF_];

// ---------------------------------------------------------------------------
// helpers
// ---------------------------------------------------------------------------
__device__ __forceinline__ float gelu_exact(float v) {
    return 0.5f * v * (1.0f + erff(v * 0.70710678118654752f));
}
__device__ __forceinline__ uint32_t smem_u32(const void* p) {
    uint32_t a;
    asm("{ .reg .u64 t; cvta.to.shared.u64 t, %1; cvt.u32.u64 %0, t; }"
        : "=r"(a) : "l"(p));
    return a;
}
__device__ __forceinline__ void cp16(uint32_t dst, const void* src) {
    asm volatile("cp.async.cg.shared.global [%0], [%1], 16;"
                 :: "r"(dst), "l"(src) : "memory");
}
__device__ __forceinline__ void mma_f16(float* d, const unsigned* a, const unsigned* b) {
    asm volatile(
        "mma.sync.aligned.m16n8k16.row.col.f32.f16.f16.f32 "
        "{%0,%1,%2,%3}, {%4,%5,%6,%7}, {%8,%9}, {%0,%1,%2,%3};\n"
        : "+f"(d[0]), "+f"(d[1]), "+f"(d[2]), "+f"(d[3])
        : "r"(a[0]), "r"(a[1]), "r"(a[2]), "r"(a[3]),
          "r"(b[0]), "r"(b[1]));
}
__device__ __forceinline__ void ldm_x4(unsigned& r0, unsigned& r1,
                                       unsigned& r2, unsigned& r3, uint32_t a) {
    asm volatile("ldmatrix.sync.aligned.m8n8.x4.shared.b16 {%0,%1,%2,%3}, [%4];"
                 : "=r"(r0), "=r"(r1), "=r"(r2), "=r"(r3) : "r"(a));
}

// ---------------------------------------------------------------------------
// h_cvt4: all four weight matrices fp32 -> half in one launch
// ---------------------------------------------------------------------------
__global__ void h_cvt4(const float* __restrict__ s0, __half* __restrict__ d0, int n0,
                       const float* __restrict__ s1, __half* __restrict__ d1, int n1,
                       const float* __restrict__ s2, __half* __restrict__ d2, int n2,
                       const float* __restrict__ s3, __half* __restrict__ d3, int n3)
{
    long long i = ((long long)blockIdx.x * 256 + threadIdx.x) * 4;
    const float* s; __half* d; long long j = i;
    if (j < n0) { s = s0; d = d0; }
    else {
        j -= n0;
        if (j < n1) { s = s1; d = d1; }
        else {
            j -= n1;
            if (j < n2) { s = s2; d = d2; }
            else {
                j -= n2;
                if (j >= n3) return;
                s = s3; d = d3;
            }
        }
    }
    float4 v = *reinterpret_cast<const float4*>(&s[j]);
    *reinterpret_cast<__half2*>(&d[j])     = __floats2half2_rn(v.x, v.y);
    *reinterpret_cast<__half2*>(&d[j + 2]) = __floats2half2_rn(v.z, v.w);
}

// ---------------------------------------------------------------------------
// zero_kernel: clears the rowsum accumulator (graph-replay safe)
// ---------------------------------------------------------------------------
__global__ void zero_kernel(float* __restrict__ p, int n)
{
    int i = blockIdx.x * 256 + threadIdx.x;
    if (i < n) p[i] = 0.f;
}

// ---------------------------------------------------------------------------
// LayerNorm: fp32 in, half out
// ---------------------------------------------------------------------------
__global__ void ln_kernel(const float* __restrict__ x,
                          const float* __restrict__ g,
                          const float* __restrict__ b,
                          __half* __restrict__ out)
{
    int row = blockIdx.x;
    long long base = (long long)row * CC;
    int t = threadIdx.x;

    float v[4];
    float s = 0.f, s2 = 0.f;
#pragma unroll
    for (int i = 0; i < 4; i++) {
        v[i] = x[base + t + i * 256];
        s  += v[i];
        s2 += v[i] * v[i];
    }
#pragma unroll
    for (int o = 16; o; o >>= 1) {
        s  += __shfl_xor_sync(0xffffffffu, s, o);
        s2 += __shfl_xor_sync(0xffffffffu, s2, o);
    }
    __shared__ float sh[16];
    int w = t >> 5, l = t & 31;
    if (l == 0) { sh[w] = s; sh[8 + w] = s2; }
    __syncthreads();
    if (t == 0) {
        float a = 0.f, c = 0.f;
#pragma unroll
        for (int i = 0; i < 8; i++) { a += sh[i]; c += sh[8 + i]; }
        sh[0] = a; sh[8] = c;
    }
    __syncthreads();
    float mu  = sh[0] * (1.0f / CC);
    float var = sh[8] * (1.0f / CC) - mu * mu;
    float inv = rsqrtf(var + 1e-5f);
#pragma unroll
    for (int i = 0; i < 4; i++) {
        int c = t + i * 256;
        out[base + c] = __float2half((v[i] - mu) * inv * g[c] + b[c]);
    }
}

// ---------------------------------------------------------------------------
// gemm_h: NT fp16 GEMM, cp.async double-buffer + ldmatrix fragments.
// A [M,K] half, B [Nc,K] half (both K-major). CTA 128x128, BK=32,
// 8 warps (2Mx4N), warp 64x32.
// Epilogue modes:
//  - expmask (emask != null): out half = mask[c] ? exp2(v*ESCALE) : 0,
//    plus fp32 atomicAdd row sums into rowsum (per-head base pre-offset).
//  - normal: bias/gelu/res, fp32 or half out.
// ---------------------------------------------------------------------------
#define ESCALE 0.18033688f   /* 0.125 * log2(e) */

__global__ __launch_bounds__(256, 2)
void gemm_h(const __half* __restrict__ A, const __half* __restrict__ Bm,
            void* __restrict__ Cv,
            int K, int lda, int ldb, int ldc,
            long long Abs, long long Ahs,
            long long Bbs, long long Bhs,
            long long Cbs, long long Chs, int Hh,
            const float* __restrict__ bias,
            const float* __restrict__ res, int act, int outHalf,
            const int* __restrict__ emask,
            float* __restrict__ rowsum)
{
    constexpr int LD = 40;
    constexpr int ROWB = LD * 2;
    constexpr int ASTG_B = 128 * ROWB;
    constexpr int STG_B = 2 * ASTG_B;
    __shared__ __half smh[2 * 256 * LD];

    int zb = blockIdx.z / Hh, zh = blockIdx.z % Hh;
    A  += zb * Abs + zh * Ahs;
    Bm += zb * Bbs + zh * Bhs;

    int t = threadIdx.x, w = t >> 5, lane = t & 31;
    int gid = lane >> 2, tig = lane & 3;
    int m0 = blockIdx.y * 128, n0 = blockIdx.x * 128;
    int wm = (w & 1) * 64, wn = (w >> 1) * 32;

    uint32_t sbase = smem_u32(smh);

    int frow = t >> 1;
    int fch  = (t & 1) * 2;

    auto fill = [&](int p, int k0) {
        uint32_t as = sbase + p * STG_B;
        uint32_t bs = as + ASTG_B;
#pragma unroll
        for (int c = 0; c < 2; c++) {
            int ch = fch + c;
            cp16(as + frow * ROWB + ch * 16,
                 &A[(long long)(m0 + frow) * lda + k0 + ch * 8]);
            cp16(bs + frow * ROWB + ch * 16,
                 &Bm[(long long)(n0 + frow) * ldb + k0 + ch * 8]);
        }
        asm volatile("cp.async.commit_group;" ::: "memory");
    };

    float acc[4][4][4] = {};

    fill(0, 0);
    int S = K / 32;
    for (int s = 0; s < S; s++) {
        int p = s & 1;
        if (s + 1 < S) {
            fill(p ^ 1, (s + 1) * 32);
            asm volatile("cp.async.wait_group 1;" ::: "memory");
        } else {
            asm volatile("cp.async.wait_group 0;" ::: "memory");
        }
        __syncthreads();

        uint32_t as = sbase + p * STG_B;
        uint32_t bs = as + ASTG_B;
#pragma unroll
        for (int kk = 0; kk < 32; kk += 16) {
            unsigned af[4][4], bf[4][2];
            int arow_l = (lane & 15);
            int akoff = kk + ((lane >> 4) << 3);
#pragma unroll
            for (int i = 0; i < 4; i++) {
                uint32_t addr = as + (wm + i * 16 + arow_l) * ROWB + akoff * 2;
                ldm_x4(af[i][0], af[i][1], af[i][2], af[i][3], addr);
            }
            int bj = (lane >> 4) & 1;
            int bkoff = kk + (((lane >> 3) & 1) << 3);
            int brow_l = lane & 7;
#pragma unroll
            for (int jp = 0; jp < 2; jp++) {
                uint32_t addr = bs + (wn + (jp * 2 + bj) * 8 + brow_l) * ROWB + bkoff * 2;
                ldm_x4(bf[jp * 2][0], bf[jp * 2][1],
                       bf[jp * 2 + 1][0], bf[jp * 2 + 1][1], addr);
            }
#pragma unroll
            for (int i = 0; i < 4; i++)
#pragma unroll
                for (int j = 0; j < 4; j++)
                    mma_f16(acc[i][j], af[i], bf[j]);
        }
        __syncthreads();
    }

    // epilogue
    float* Cf = (float*)Cv;
    __half* Ch = (__half*)Cv;
    long long coff = zb * Cbs + zh * Chs;

    if (emask) {
        const int* mrow = emask + (long long)zb * NN_;
        float* rs = rowsum + (long long)(zb * Hh + zh) * NN_;
#pragma unroll
        for (int i = 0; i < 4; i++) {
            int r1 = m0 + wm + i * 16 + gid;
            int r2 = r1 + 8;
            float rs1 = 0.f, rs2 = 0.f;
#pragma unroll
            for (int j = 0; j < 4; j++) {
                int c = n0 + wn + j * 8 + 2 * tig;
                float v0 = acc[i][j][0], v1 = acc[i][j][1];
                float v2 = acc[i][j][2], v3 = acc[i][j][3];
                bool m0b = mrow[c] != 0, m1b = mrow[c + 1] != 0;
                v0 = m0b ? exp2f(v0 * ESCALE) : 0.f;
                v1 = m1b ? exp2f(v1 * ESCALE) : 0.f;
                v2 = m0b ? exp2f(v2 * ESCALE) : 0.f;
                v3 = m1b ? exp2f(v3 * ESCALE) : 0.f;
                long long i1 = coff + (long long)r1 * ldc + c;
                long long i2 = coff + (long long)r2 * ldc + c;
                *reinterpret_cast<__half2*>(&Ch[i1]) = __floats2half2_rn(v0, v1);
                *reinterpret_cast<__half2*>(&Ch[i2]) = __floats2half2_rn(v2, v3);
                rs1 += v0 + v1;
                rs2 += v2 + v3;
            }
            // reduce across the 4 lanes (tig) sharing each row
            rs1 += __shfl_xor_sync(0xffffffffu, rs1, 1);
            rs1 += __shfl_xor_sync(0xffffffffu, rs1, 2);
            rs2 += __shfl_xor_sync(0xffffffffu, rs2, 1);
            rs2 += __shfl_xor_sync(0xffffffffu, rs2, 2);
            if (tig == 0) {
                atomicAdd(&rs[r1], rs1);
                atomicAdd(&rs[r2], rs2);
            }
        }
        return;
    }

#pragma unroll
    for (int i = 0; i < 4; i++) {
        int r1 = m0 + wm + i * 16 + gid;
        int r2 = r1 + 8;
#pragma unroll
        for (int j = 0; j < 4; j++) {
            int c = n0 + wn + j * 8 + 2 * tig;
            float v0 = acc[i][j][0], v1 = acc[i][j][1];
            float v2 = acc[i][j][2], v3 = acc[i][j][3];
            long long i1 = coff + (long long)r1 * ldc + c;
            long long i2 = coff + (long long)r2 * ldc + c;
            if (bias) {
                float b0 = bias[c], b1 = bias[c + 1];
                v0 += b0; v1 += b1; v2 += b0; v3 += b1;
            }
            if (act) {
                v0 = gelu_exact(v0); v1 = gelu_exact(v1);
                v2 = gelu_exact(v2); v3 = gelu_exact(v3);
            }
            if (res) {
                float2 ra = *reinterpret_cast<const float2*>(&res[(long long)r1 * ldc + c]);
                float2 rb = *reinterpret_cast<const float2*>(&res[(long long)r2 * ldc + c]);
                v0 += ra.x; v1 += ra.y; v2 += rb.x; v3 += rb.y;
            }
            if (outHalf) {
                *reinterpret_cast<__half2*>(&Ch[i1]) = __floats2half2_rn(v0, v1);
                *reinterpret_cast<__half2*>(&Ch[i2]) = __floats2half2_rn(v2, v3);
            } else {
                float2 o1 = {v0, v1}, o2 = {v2, v3};
                *reinterpret_cast<float2*>(&Cf[i1]) = o1;
                *reinterpret_cast<float2*>(&Cf[i2]) = o2;
            }
        }
    }
}

// ---------------------------------------------------------------------------
// gemm_avh: AV fp16 GEMM on UNNORMALIZED u, normalized by 1/rowsum.
// FUSED: while streaming u tiles, writes normalized fp32 attn.
// A [N,N] half, V rows=k cols=d half (transposed into smem). CTA 128x64.
// ---------------------------------------------------------------------------
__global__ __launch_bounds__(256, 2)
void gemm_avh(const __half* __restrict__ A, const __half* __restrict__ V,
              __half* __restrict__ C,
              const float* __restrict__ rowsum,
              float* __restrict__ attn_out,
              int K, int lda, int ldb, int ldc,
              long long Abs, long long Ahs,
              long long Bbs, long long Bhs,
              long long Cbs, long long Chs, int Hh)
{
    constexpr int LD = 40;
    constexpr int ROWB = LD * 2;
    __shared__ __half As[128 * LD];
    __shared__ __half Bs[64 * LD];

    int zb = blockIdx.z / Hh, zh = blockIdx.z % Hh;
    A += zb * Abs + zh * Ahs;
    V += zb * Bbs + zh * Bhs;
    C += zb * Cbs + zh * Chs;
    rowsum += (long long)(zb * Hh + zh) * NN_;
    attn_out += (long long)(zb * Hh + zh) * NN_ * NN_;

    int t = threadIdx.x, w = t >> 5, lane = t & 31;
    int gid = lane >> 2, tig = lane & 3;
    int m0 = blockIdx.y * 128;
    int wm = (w & 3) * 32, wn = (w >> 2) * 32;

    int lrow = t >> 2;          // 0..63
    int lcol = (t & 3) * 8;
    int vmr = t >> 3;
    int vdc = (t & 7) * 8;

    float is0 = 1.0f / rowsum[m0 + lrow];
    float is1 = 1.0f / rowsum[m0 + lrow + 64];

    uint32_t asb = smem_u32(As);
    uint32_t bsb = smem_u32(Bs);

    float acc[2][4][4] = {};

    for (int k0 = 0; k0 < K; k0 += 32) {
#pragma unroll
        for (int i = 0; i < 2; i++) {
            int r = lrow + 64 * i;
            uint4 u4 = *reinterpret_cast<const uint4*>(&A[(long long)(m0 + r) * lda + k0 + lcol]);
            *reinterpret_cast<uint4*>(&As[r * LD + lcol]) = u4;
            float isr = i ? is1 : is0;
            const __half2* h2 = reinterpret_cast<const __half2*>(&u4);
            float2 f0 = __half22float2(h2[0]);
            float2 f1 = __half22float2(h2[1]);
            float2 f2 = __half22float2(h2[2]);
            float2 f3 = __half22float2(h2[3]);
            float4 o1 = {f0.x * isr, f0.y * isr, f1.x * isr, f1.y * isr};
            float4 o2 = {f2.x * isr, f2.y * isr, f3.x * isr, f3.y * isr};
            long long ab = (long long)(m0 + r) * NN_ + k0 + lcol;
            *reinterpret_cast<float4*>(&attn_out[ab])     = o1;
            *reinterpret_cast<float4*>(&attn_out[ab + 4]) = o2;
        }
        {
            uint4 u = *reinterpret_cast<const uint4*>(&V[(long long)(k0 + vmr) * ldb + vdc]);
            const __half* hv = reinterpret_cast<const __half*>(&u);
#pragma unroll
            for (int j = 0; j < 8; j++)
                Bs[(vdc + j) * LD + vmr] = hv[j];
        }
        __syncthreads();

#pragma unroll
        for (int kk = 0; kk < 32; kk += 16) {
            unsigned af[2][4], bf[4][2];
            int arow_l = (lane & 15);
            int akoff = kk + ((lane >> 4) << 3);
#pragma unroll
            for (int i = 0; i < 2; i++) {
                uint32_t addr = asb + (wm + i * 16 + arow_l) * ROWB + akoff * 2;
                ldm_x4(af[i][0], af[i][1], af[i][2], af[i][3], addr);
            }
            int bj = (lane >> 4) & 1;
            int bkoff = kk + (((lane >> 3) & 1) << 3);
            int brow_l = lane & 7;
#pragma unroll
            for (int jp = 0; jp < 2; jp++) {
                uint32_t addr = bsb + (wn + (jp * 2 + bj) * 8 + brow_l) * ROWB + bkoff * 2;
                ldm_x4(bf[jp * 2][0], bf[jp * 2][1],
                       bf[jp * 2 + 1][0], bf[jp * 2 + 1][1], addr);
            }
#pragma unroll
            for (int i = 0; i < 2; i++)
#pragma unroll
                for (int j = 0; j < 4; j++)
                    mma_f16(acc[i][j], af[i], bf[j]);
        }
        __syncthreads();
    }

#pragma unroll
    for (int i = 0; i < 2; i++) {
        int r1 = m0 + wm + i * 16 + gid;
        int r2 = r1 + 8;
        float s1 = 1.0f / rowsum[r1];
        float s2 = 1.0f / rowsum[r2];
#pragma unroll
        for (int j = 0; j < 4; j++) {
            int c = wn + j * 8 + 2 * tig;
            *reinterpret_cast<__half2*>(&C[(long long)r1 * ldc + c]) =
                __floats2half2_rn(acc[i][j][0] * s1, acc[i][j][1] * s1);
            *reinterpret_cast<__half2*>(&C[(long long)r2 * ldc + c]) =
                __floats2half2_rn(acc[i][j][2] * s2, acc[i][j][3] * s2);
        }
    }
}

// ---------------------------------------------------------------------------
// Launch
// ---------------------------------------------------------------------------
extern "C" void kernel_launch(void* const* d_in, const int* in_sizes, int n_in,
                              void* d_out, int out_size)
{
    const float* x      = (const float*)d_in[0];
    const int*   mask   = (const int*)  d_in[1];
    const float* qkv_w  = (const float*)d_in[2];
    const float* proj_w = (const float*)d_in[3];
    const float* proj_b = (const float*)d_in[4];
    const float* ln1_g  = (const float*)d_in[5];
    const float* ln1_b  = (const float*)d_in[6];
    const float* ln2_g  = (const float*)d_in[7];
    const float* ln2_b  = (const float*)d_in[8];
    const float* fc1_w  = (const float*)d_in[9];
    const float* fc1_b  = (const float*)d_in[10];
    const float* fc2_w  = (const float*)d_in[11];
    const float* fc2_b  = (const float*)d_in[12];

    float* out_x    = (float*)d_out;
    float* out_attn = out_x + (long long)Bb * NN_ * CC;

    __half *p_ln, *p_qkv, *p_ao, *p_h, *p_ph, *p_wq, *p_wp, *p_w1, *p_w2;
    float *p_x1, *p_rs;
    cudaGetSymbolAddress((void**)&p_ln,  g_lnh);
    cudaGetSymbolAddress((void**)&p_qkv, g_qkvh);
    cudaGetSymbolAddress((void**)&p_ao,  g_aoh);
    cudaGetSymbolAddress((void**)&p_x1,  g_x1);
    cudaGetSymbolAddress((void**)&p_h,   g_hbufh);
    cudaGetSymbolAddress((void**)&p_ph,  g_ph);
    cudaGetSymbolAddress((void**)&p_rs,  g_rowsum);
    cudaGetSymbolAddress((void**)&p_wq,  g_wq);
    cudaGetSymbolAddress((void**)&p_wp,  g_wp);
    cudaGetSymbolAddress((void**)&p_w1,  g_w1);
    cudaGetSymbolAddress((void**)&p_w2,  g_w2);

    const int M  = Bb * NN_;                 // 4096
    const long long ZERO = 0;
    const long long NC3 = (long long)NN_ * 3 * CC;
    const int NROWS = Bb * HH * NN_;         // 65536

    // 0) all weights -> half (single launch) ; zero rowsum accumulator
    {
        int n0 = 3 * CC * CC, n1 = CC * CC, n2 = DFF_ * CC, n3 = CC * DFF_;
        long long ntot = (long long)n0 + n1 + n2 + n3;
        int blocks = (int)((ntot / 4 + 255) / 256);
        h_cvt4<<<blocks, 256>>>(qkv_w, p_wq, n0, proj_w, p_wp, n1,
                                fc1_w, p_w1, n2, fc2_w, p_w2, n3);
        zero_kernel<<<(NROWS + 255) / 256, 256>>>(p_rs, NROWS);
    }

    // 1) LN1 -> half
    ln_kernel<<<M, 256>>>(x, ln1_g, ln1_b, p_ln);

    // 2) QKV
    {
        dim3 grid(3 * CC / 128, M / 128, 1);
        gemm_h<<<grid, 256>>>(p_ln, p_wq, p_qkv,
            CC, CC, CC, 3 * CC,
            ZERO, ZERO, ZERO, ZERO, ZERO, ZERO, 1,
            nullptr, nullptr, 0, 1, nullptr, nullptr);
    }

    // 3) QK^T per head -> g_ph = half(exp(masked scaled logits)) + rowsums
    {
        dim3 grid(NN_ / 128, NN_ / 128, Bb * HH);
        gemm_h<<<grid, 256>>>(p_qkv, p_qkv + CC, p_ph,
            DD, 3 * CC, 3 * CC, NN_,
            NC3, DD, NC3, DD,
            (long long)HH * NN_ * NN_, (long long)NN_ * NN_, HH,
            nullptr, nullptr, 0, 1, mask, p_rs);
    }

    // 4) AV per head on unnormalized u (scaled by 1/rowsum) + fused attn write
    {
        dim3 grid(1, NN_ / 128, Bb * HH);
        gemm_avh<<<grid, 256>>>(p_ph, p_qkv + 2 * CC, p_ao, p_rs, out_attn,
            NN_, NN_, 3 * CC, CC,
            (long long)HH * NN_ * NN_, (long long)NN_ * NN_,
            NC3, DD,
            (long long)NN_ * CC, DD, HH);
    }

    // 5) proj + residual -> x1 (fp32)
    {
        dim3 grid(CC / 128, M / 128, 1);
        gemm_h<<<grid, 256>>>(p_ao, p_wp, p_x1,
            CC, CC, CC, CC,
            ZERO, ZERO, ZERO, ZERO, ZERO, ZERO, 1,
            proj_b, x, 0, 0, nullptr, nullptr);
    }

    // 6) LN2 -> half
    ln_kernel<<<M, 256>>>(p_x1, ln2_g, ln2_b, p_ln);

    // 7) FC1 + GELU -> half
    {
        dim3 grid(DFF_ / 128, M / 128, 1);
        gemm_h<<<grid, 256>>>(p_ln, p_w1, p_h,
            CC, CC, CC, DFF_,
            ZERO, ZERO, ZERO, ZERO, ZERO, ZERO, 1,
            fc1_b, nullptr, 1, 1, nullptr, nullptr);
    }

    // 8) FC2 + residual -> out_x (fp32)
    {
        dim3 grid(CC / 128, M / 128, 1);
        gemm_h<<<grid, 256>>>(p_h, p_w2, out_x,
            DFF_, DFF_, DFF_, CC,
            ZERO, ZERO, ZERO, ZERO, ZERO, ZERO, 1,
            fc2_b, p_x1, 0, 0, nullptr, nullptr);
    }
}

// round 12
// speedup vs baseline: 1.1365x; 1.0261x over previous
#include <cuda_runtime.h>
#include <cuda_fp16.h>
#include <math.h>
#include <stdint.h>

// Problem constants
#define Bb   2
#define NN_  2048
#define CC   1024
#define HH   16
#define DD   64
#define DFF_ 4096

// Scratch buffers (static device globals — allocation-free rule)
__device__ __half g_lnh[Bb * NN_ * CC];
__device__ __half g_qkvh[Bb * NN_ * 3 * CC];
__device__ __half g_aoh[Bb * NN_ * CC];
__device__ float  g_x1[Bb * NN_ * CC];
__device__ __half g_hbufh[Bb * NN_ * DFF_];
__device__ __half g_ph[(long long)Bb * HH * NN_ * NN_];  // unnormalized exp (half)
__device__ float  g_rowsum[Bb * HH * NN_];               // fp32 row sums (atomic)
__device__ __half g_wq[3 * CC * CC];
__device__ __half g_wp[CC * CC];
__device__ __half g_w1[DFF_ * CC];
__device__ __half g_w2[CC * DFF_];

// ---------------------------------------------------------------------------
// helpers
// ---------------------------------------------------------------------------
__device__ __forceinline__ float gelu_exact(float v) {
    return 0.5f * v * (1.0f + erff(v * 0.70710678118654752f));
}
__device__ __forceinline__ uint32_t smem_u32(const void* p) {
    uint32_t a;
    asm("{ .reg .u64 t; cvta.to.shared.u64 t, %1; cvt.u32.u64 %0, t; }"
        : "=r"(a) : "l"(p));
    return a;
}
__device__ __forceinline__ void cp16(uint32_t dst, const void* src) {
    asm volatile("cp.async.cg.shared.global [%0], [%1], 16;"
                 :: "r"(dst), "l"(src) : "memory");
}
__device__ __forceinline__ void mma_f16(float* d, const unsigned* a, const unsigned* b) {
    asm volatile(
        "mma.sync.aligned.m16n8k16.row.col.f32.f16.f16.f32 "
        "{%0,%1,%2,%3}, {%4,%5,%6,%7}, {%8,%9}, {%0,%1,%2,%3};\n"
        : "+f"(d[0]), "+f"(d[1]), "+f"(d[2]), "+f"(d[3])
        : "r"(a[0]), "r"(a[1]), "r"(a[2]), "r"(a[3]),
          "r"(b[0]), "r"(b[1]));
}
__device__ __forceinline__ void ldm_x4(unsigned& r0, unsigned& r1,
                                       unsigned& r2, unsigned& r3, uint32_t a) {
    asm volatile("ldmatrix.sync.aligned.m8n8.x4.shared.b16 {%0,%1,%2,%3}, [%4];"
                 : "=r"(r0), "=r"(r1), "=r"(r2), "=r"(r3) : "r"(a));
}

// ---------------------------------------------------------------------------
// h_cvt4: all four weight matrices fp32 -> half in one launch
// ---------------------------------------------------------------------------
__global__ void h_cvt4(const float* __restrict__ s0, __half* __restrict__ d0, int n0,
                       const float* __restrict__ s1, __half* __restrict__ d1, int n1,
                       const float* __restrict__ s2, __half* __restrict__ d2, int n2,
                       const float* __restrict__ s3, __half* __restrict__ d3, int n3)
{
    long long i = ((long long)blockIdx.x * 256 + threadIdx.x) * 4;
    const float* s; __half* d; long long j = i;
    if (j < n0) { s = s0; d = d0; }
    else {
        j -= n0;
        if (j < n1) { s = s1; d = d1; }
        else {
            j -= n1;
            if (j < n2) { s = s2; d = d2; }
            else {
                j -= n2;
                if (j >= n3) return;
                s = s3; d = d3;
            }
        }
    }
    float4 v = *reinterpret_cast<const float4*>(&s[j]);
    *reinterpret_cast<__half2*>(&d[j])     = __floats2half2_rn(v.x, v.y);
    *reinterpret_cast<__half2*>(&d[j + 2]) = __floats2half2_rn(v.z, v.w);
}

// ---------------------------------------------------------------------------
// zero_kernel
// ---------------------------------------------------------------------------
__global__ void zero_kernel(float* __restrict__ p, int n)
{
    int i = blockIdx.x * 256 + threadIdx.x;
    if (i < n) p[i] = 0.f;
}

// ---------------------------------------------------------------------------
// LayerNorm: fp32 in, half out
// ---------------------------------------------------------------------------
__global__ void ln_kernel(const float* __restrict__ x,
                          const float* __restrict__ g,
                          const float* __restrict__ b,
                          __half* __restrict__ out)
{
    int row = blockIdx.x;
    long long base = (long long)row * CC;
    int t = threadIdx.x;

    float v[4];
    float s = 0.f, s2 = 0.f;
#pragma unroll
    for (int i = 0; i < 4; i++) {
        v[i] = x[base + t + i * 256];
        s  += v[i];
        s2 += v[i] * v[i];
    }
#pragma unroll
    for (int o = 16; o; o >>= 1) {
        s  += __shfl_xor_sync(0xffffffffu, s, o);
        s2 += __shfl_xor_sync(0xffffffffu, s2, o);
    }
    __shared__ float sh[16];
    int w = t >> 5, l = t & 31;
    if (l == 0) { sh[w] = s; sh[8 + w] = s2; }
    __syncthreads();
    if (t == 0) {
        float a = 0.f, c = 0.f;
#pragma unroll
        for (int i = 0; i < 8; i++) { a += sh[i]; c += sh[8 + i]; }
        sh[0] = a; sh[8] = c;
    }
    __syncthreads();
    float mu  = sh[0] * (1.0f / CC);
    float var = sh[8] * (1.0f / CC) - mu * mu;
    float inv = rsqrtf(var + 1e-5f);
#pragma unroll
    for (int i = 0; i < 4; i++) {
        int c = t + i * 256;
        out[base + c] = __float2half((v[i] - mu) * inv * g[c] + b[c]);
    }
}

// ---------------------------------------------------------------------------
// gemm_h: NT fp16 GEMM, 3-stage cp.async pipeline + ldmatrix fragments.
// One __syncthreads per BK iteration (fill of a stage only happens after the
// sync that proves all warps finished computing on it).
// A [M,K] half, B [Nc,K] half (both K-major). CTA 128x128, BK=32,
// 8 warps (2Mx4N), warp 64x32.
// ---------------------------------------------------------------------------
#define ESCALE 0.18033688f   /* 0.125 * log2(e) */

__global__ __launch_bounds__(256, 2)
void gemm_h(const __half* __restrict__ A, const __half* __restrict__ Bm,
            void* __restrict__ Cv,
            int K, int lda, int ldb, int ldc,
            long long Abs, long long Ahs,
            long long Bbs, long long Bhs,
            long long Cbs, long long Chs, int Hh,
            const float* __restrict__ bias,
            const float* __restrict__ res, int act, int outHalf,
            const int* __restrict__ emask,
            float* __restrict__ rowsum)
{
    constexpr int LD = 40;
    constexpr int ROWB = LD * 2;
    constexpr int ASTG_B = 128 * ROWB;      // 10240 B
    constexpr int STG_B = 2 * ASTG_B;       // 20480 B per stage
    constexpr int NS = 3;
    __shared__ __half smh[NS * 256 * LD];   // 61440 B

    int zb = blockIdx.z / Hh, zh = blockIdx.z % Hh;
    A  += zb * Abs + zh * Ahs;
    Bm += zb * Bbs + zh * Bhs;

    int t = threadIdx.x, w = t >> 5, lane = t & 31;
    int gid = lane >> 2, tig = lane & 3;
    int m0 = blockIdx.y * 128, n0 = blockIdx.x * 128;
    int wm = (w & 1) * 64, wn = (w >> 1) * 32;

    uint32_t sbase = smem_u32(smh);

    int frow = t >> 1;
    int fch  = (t & 1) * 2;

    int S = K / 32;

    auto fill = [&](int stg) {               // stg = absolute K-slab index
        if (stg < S) {
            int p = stg % NS;
            int k0 = stg * 32;
            uint32_t as = sbase + p * STG_B;
            uint32_t bs = as + ASTG_B;
#pragma unroll
            for (int c = 0; c < 2; c++) {
                int ch = fch + c;
                cp16(as + frow * ROWB + ch * 16,
                     &A[(long long)(m0 + frow) * lda + k0 + ch * 8]);
                cp16(bs + frow * ROWB + ch * 16,
                     &Bm[(long long)(n0 + frow) * ldb + k0 + ch * 8]);
            }
        }
        asm volatile("cp.async.commit_group;" ::: "memory");  // empty group ok
    };

    float acc[4][4][4] = {};

    // prologue: stages 0, 1
    fill(0);
    fill(1);

    for (int s = 0; s < S; s++) {
        asm volatile("cp.async.wait_group 1;" ::: "memory");  // stage s ready
        __syncthreads();
        fill(s + 2);    // safe: sync proved all warps done computing buffer (s+2)%3

        int p = s % NS;
        uint32_t as = sbase + p * STG_B;
        uint32_t bs = as + ASTG_B;
#pragma unroll
        for (int kk = 0; kk < 32; kk += 16) {
            unsigned af[4][4], bf[4][2];
            int arow_l = (lane & 15);
            int akoff = kk + ((lane >> 4) << 3);
#pragma unroll
            for (int i = 0; i < 4; i++) {
                uint32_t addr = as + (wm + i * 16 + arow_l) * ROWB + akoff * 2;
                ldm_x4(af[i][0], af[i][1], af[i][2], af[i][3], addr);
            }
            int bj = (lane >> 4) & 1;
            int bkoff = kk + (((lane >> 3) & 1) << 3);
            int brow_l = lane & 7;
#pragma unroll
            for (int jp = 0; jp < 2; jp++) {
                uint32_t addr = bs + (wn + (jp * 2 + bj) * 8 + brow_l) * ROWB + bkoff * 2;
                ldm_x4(bf[jp * 2][0], bf[jp * 2][1],
                       bf[jp * 2 + 1][0], bf[jp * 2 + 1][1], addr);
            }
#pragma unroll
            for (int i = 0; i < 4; i++)
#pragma unroll
                for (int j = 0; j < 4; j++)
                    mma_f16(acc[i][j], af[i], bf[j]);
        }
    }

    // epilogue
    float* Cf = (float*)Cv;
    __half* Ch = (__half*)Cv;
    long long coff = zb * Cbs + zh * Chs;

    if (emask) {
        const int* mrow = emask + (long long)zb * NN_;
        float* rs = rowsum + (long long)(zb * Hh + zh) * NN_;
#pragma unroll
        for (int i = 0; i < 4; i++) {
            int r1 = m0 + wm + i * 16 + gid;
            int r2 = r1 + 8;
            float rs1 = 0.f, rs2 = 0.f;
#pragma unroll
            for (int j = 0; j < 4; j++) {
                int c = n0 + wn + j * 8 + 2 * tig;
                float v0 = acc[i][j][0], v1 = acc[i][j][1];
                float v2 = acc[i][j][2], v3 = acc[i][j][3];
                bool m0b = mrow[c] != 0, m1b = mrow[c + 1] != 0;
                v0 = m0b ? exp2f(v0 * ESCALE) : 0.f;
                v1 = m1b ? exp2f(v1 * ESCALE) : 0.f;
                v2 = m0b ? exp2f(v2 * ESCALE) : 0.f;
                v3 = m1b ? exp2f(v3 * ESCALE) : 0.f;
                long long i1 = coff + (long long)r1 * ldc + c;
                long long i2 = coff + (long long)r2 * ldc + c;
                *reinterpret_cast<__half2*>(&Ch[i1]) = __floats2half2_rn(v0, v1);
                *reinterpret_cast<__half2*>(&Ch[i2]) = __floats2half2_rn(v2, v3);
                rs1 += v0 + v1;
                rs2 += v2 + v3;
            }
            rs1 += __shfl_xor_sync(0xffffffffu, rs1, 1);
            rs1 += __shfl_xor_sync(0xffffffffu, rs1, 2);
            rs2 += __shfl_xor_sync(0xffffffffu, rs2, 1);
            rs2 += __shfl_xor_sync(0xffffffffu, rs2, 2);
            if (tig == 0) {
                atomicAdd(&rs[r1], rs1);
                atomicAdd(&rs[r2], rs2);
            }
        }
        return;
    }

#pragma unroll
    for (int i = 0; i < 4; i++) {
        int r1 = m0 + wm + i * 16 + gid;
        int r2 = r1 + 8;
#pragma unroll
        for (int j = 0; j < 4; j++) {
            int c = n0 + wn + j * 8 + 2 * tig;
            float v0 = acc[i][j][0], v1 = acc[i][j][1];
            float v2 = acc[i][j][2], v3 = acc[i][j][3];
            long long i1 = coff + (long long)r1 * ldc + c;
            long long i2 = coff + (long long)r2 * ldc + c;
            if (bias) {
                float b0 = bias[c], b1 = bias[c + 1];
                v0 += b0; v1 += b1; v2 += b0; v3 += b1;
            }
            if (act) {
                v0 = gelu_exact(v0); v1 = gelu_exact(v1);
                v2 = gelu_exact(v2); v3 = gelu_exact(v3);
            }
            if (res) {
                float2 ra = *reinterpret_cast<const float2*>(&res[(long long)r1 * ldc + c]);
                float2 rb = *reinterpret_cast<const float2*>(&res[(long long)r2 * ldc + c]);
                v0 += ra.x; v1 += ra.y; v2 += rb.x; v3 += rb.y;
            }
            if (outHalf) {
                *reinterpret_cast<__half2*>(&Ch[i1]) = __floats2half2_rn(v0, v1);
                *reinterpret_cast<__half2*>(&Ch[i2]) = __floats2half2_rn(v2, v3);
            } else {
                float2 o1 = {v0, v1}, o2 = {v2, v3};
                *reinterpret_cast<float2*>(&Cf[i1]) = o1;
                *reinterpret_cast<float2*>(&Cf[i2]) = o2;
            }
        }
    }
}

// ---------------------------------------------------------------------------
// gemm_avh: AV fp16 GEMM on UNNORMALIZED u, normalized by 1/rowsum.
// FUSED: writes normalized fp32 attn while streaming u tiles.
// ---------------------------------------------------------------------------
__global__ __launch_bounds__(256, 2)
void gemm_avh(const __half* __restrict__ A, const __half* __restrict__ V,
              __half* __restrict__ C,
              const float* __restrict__ rowsum,
              float* __restrict__ attn_out,
              int K, int lda, int ldb, int ldc,
              long long Abs, long long Ahs,
              long long Bbs, long long Bhs,
              long long Cbs, long long Chs, int Hh)
{
    constexpr int LD = 40;
    constexpr int ROWB = LD * 2;
    __shared__ __half As[128 * LD];
    __shared__ __half Bs[64 * LD];

    int zb = blockIdx.z / Hh, zh = blockIdx.z % Hh;
    A += zb * Abs + zh * Ahs;
    V += zb * Bbs + zh * Bhs;
    C += zb * Cbs + zh * Chs;
    rowsum += (long long)(zb * Hh + zh) * NN_;
    attn_out += (long long)(zb * Hh + zh) * NN_ * NN_;

    int t = threadIdx.x, w = t >> 5, lane = t & 31;
    int gid = lane >> 2, tig = lane & 3;
    int m0 = blockIdx.y * 128;
    int wm = (w & 3) * 32, wn = (w >> 2) * 32;

    int lrow = t >> 2;
    int lcol = (t & 3) * 8;
    int vmr = t >> 3;
    int vdc = (t & 7) * 8;

    float is0 = 1.0f / rowsum[m0 + lrow];
    float is1 = 1.0f / rowsum[m0 + lrow + 64];

    uint32_t asb = smem_u32(As);
    uint32_t bsb = smem_u32(Bs);

    float acc[2][4][4] = {};

    for (int k0 = 0; k0 < K; k0 += 32) {
#pragma unroll
        for (int i = 0; i < 2; i++) {
            int r = lrow + 64 * i;
            uint4 u4 = *reinterpret_cast<const uint4*>(&A[(long long)(m0 + r) * lda + k0 + lcol]);
            *reinterpret_cast<uint4*>(&As[r * LD + lcol]) = u4;
            float isr = i ? is1 : is0;
            const __half2* h2 = reinterpret_cast<const __half2*>(&u4);
            float2 f0 = __half22float2(h2[0]);
            float2 f1 = __half22float2(h2[1]);
            float2 f2 = __half22float2(h2[2]);
            float2 f3 = __half22float2(h2[3]);
            float4 o1 = {f0.x * isr, f0.y * isr, f1.x * isr, f1.y * isr};
            float4 o2 = {f2.x * isr, f2.y * isr, f3.x * isr, f3.y * isr};
            long long ab = (long long)(m0 + r) * NN_ + k0 + lcol;
            *reinterpret_cast<float4*>(&attn_out[ab])     = o1;
            *reinterpret_cast<float4*>(&attn_out[ab + 4]) = o2;
        }
        {
            uint4 u = *reinterpret_cast<const uint4*>(&V[(long long)(k0 + vmr) * ldb + vdc]);
            const __half* hv = reinterpret_cast<const __half*>(&u);
#pragma unroll
            for (int j = 0; j < 8; j++)
                Bs[(vdc + j) * LD + vmr] = hv[j];
        }
        __syncthreads();

#pragma unroll
        for (int kk = 0; kk < 32; kk += 16) {
            unsigned af[2][4], bf[4][2];
            int arow_l = (lane & 15);
            int akoff = kk + ((lane >> 4) << 3);
#pragma unroll
            for (int i = 0; i < 2; i++) {
                uint32_t addr = asb + (wm + i * 16 + arow_l) * ROWB + akoff * 2;
                ldm_x4(af[i][0], af[i][1], af[i][2], af[i][3], addr);
            }
            int bj = (lane >> 4) & 1;
            int bkoff = kk + (((lane >> 3) & 1) << 3);
            int brow_l = lane & 7;
#pragma unroll
            for (int jp = 0; jp < 2; jp++) {
                uint32_t addr = bsb + (wn + (jp * 2 + bj) * 8 + brow_l) * ROWB + bkoff * 2;
                ldm_x4(bf[jp * 2][0], bf[jp * 2][1],
                       bf[jp * 2 + 1][0], bf[jp * 2 + 1][1], addr);
            }
#pragma unroll
            for (int i = 0; i < 2; i++)
#pragma unroll
                for (int j = 0; j < 4; j++)
                    mma_f16(acc[i][j], af[i], bf[j]);
        }
        __syncthreads();
    }

#pragma unroll
    for (int i = 0; i < 2; i++) {
        int r1 = m0 + wm + i * 16 + gid;
        int r2 = r1 + 8;
        float s1 = 1.0f / rowsum[r1];
        float s2 = 1.0f / rowsum[r2];
#pragma unroll
        for (int j = 0; j < 4; j++) {
            int c = wn + j * 8 + 2 * tig;
            *reinterpret_cast<__half2*>(&C[(long long)r1 * ldc + c]) =
                __floats2half2_rn(acc[i][j][0] * s1, acc[i][j][1] * s1);
            *reinterpret_cast<__half2*>(&C[(long long)r2 * ldc + c]) =
                __floats2half2_rn(acc[i][j][2] * s2, acc[i][j][3] * s2);
        }
    }
}

// ---------------------------------------------------------------------------
// Launch
// ---------------------------------------------------------------------------
extern "C" void kernel_launch(void* const* d_in, const int* in_sizes, int n_in,
                              void* d_out, int out_size)
{
    const float* x      = (const float*)d_in[0];
    const int*   mask   = (const int*)  d_in[1];
    const float* qkv_w  = (const float*)d_in[2];
    const float* proj_w = (const float*)d_in[3];
    const float* proj_b = (const float*)d_in[4];
    const float* ln1_g  = (const float*)d_in[5];
    const float* ln1_b  = (const float*)d_in[6];
    const float* ln2_g  = (const float*)d_in[7];
    const float* ln2_b  = (const float*)d_in[8];
    const float* fc1_w  = (const float*)d_in[9];
    const float* fc1_b  = (const float*)d_in[10];
    const float* fc2_w  = (const float*)d_in[11];
    const float* fc2_b  = (const float*)d_in[12];

    float* out_x    = (float*)d_out;
    float* out_attn = out_x + (long long)Bb * NN_ * CC;

    __half *p_ln, *p_qkv, *p_ao, *p_h, *p_ph, *p_wq, *p_wp, *p_w1, *p_w2;
    float *p_x1, *p_rs;
    cudaGetSymbolAddress((void**)&p_ln,  g_lnh);
    cudaGetSymbolAddress((void**)&p_qkv, g_qkvh);
    cudaGetSymbolAddress((void**)&p_ao,  g_aoh);
    cudaGetSymbolAddress((void**)&p_x1,  g_x1);
    cudaGetSymbolAddress((void**)&p_h,   g_hbufh);
    cudaGetSymbolAddress((void**)&p_ph,  g_ph);
    cudaGetSymbolAddress((void**)&p_rs,  g_rowsum);
    cudaGetSymbolAddress((void**)&p_wq,  g_wq);
    cudaGetSymbolAddress((void**)&p_wp,  g_wp);
    cudaGetSymbolAddress((void**)&p_w1,  g_w1);
    cudaGetSymbolAddress((void**)&p_w2,  g_w2);

    const int M  = Bb * NN_;                 // 4096
    const long long ZERO = 0;
    const long long NC3 = (long long)NN_ * 3 * CC;
    const int NROWS = Bb * HH * NN_;

    // 0) all weights -> half ; zero rowsum accumulator
    {
        int n0 = 3 * CC * CC, n1 = CC * CC, n2 = DFF_ * CC, n3 = CC * DFF_;
        long long ntot = (long long)n0 + n1 + n2 + n3;
        int blocks = (int)((ntot / 4 + 255) / 256);
        h_cvt4<<<blocks, 256>>>(qkv_w, p_wq, n0, proj_w, p_wp, n1,
                                fc1_w, p_w1, n2, fc2_w, p_w2, n3);
        zero_kernel<<<(NROWS + 255) / 256, 256>>>(p_rs, NROWS);
    }

    // 1) LN1 -> half
    ln_kernel<<<M, 256>>>(x, ln1_g, ln1_b, p_ln);

    // 2) QKV
    {
        dim3 grid(3 * CC / 128, M / 128, 1);
        gemm_h<<<grid, 256>>>(p_ln, p_wq, p_qkv,
            CC, CC, CC, 3 * CC,
            ZERO, ZERO, ZERO, ZERO, ZERO, ZERO, 1,
            nullptr, nullptr, 0, 1, nullptr, nullptr);
    }

    // 3) QK^T per head -> g_ph = half(exp(masked scaled logits)) + rowsums
    {
        dim3 grid(NN_ / 128, NN_ / 128, Bb * HH);
        gemm_h<<<grid, 256>>>(p_qkv, p_qkv + CC, p_ph,
            DD, 3 * CC, 3 * CC, NN_,
            NC3, DD, NC3, DD,
            (long long)HH * NN_ * NN_, (long long)NN_ * NN_, HH,
            nullptr, nullptr, 0, 1, mask, p_rs);
    }

    // 4) AV per head + fused attn write
    {
        dim3 grid(1, NN_ / 128, Bb * HH);
        gemm_avh<<<grid, 256>>>(p_ph, p_qkv + 2 * CC, p_ao, p_rs, out_attn,
            NN_, NN_, 3 * CC, CC,
            (long long)HH * NN_ * NN_, (long long)NN_ * NN_,
            NC3, DD,
            (long long)NN_ * CC, DD, HH);
    }

    // 5) proj + residual -> x1 (fp32)
    {
        dim3 grid(CC / 128, M / 128, 1);
        gemm_h<<<grid, 256>>>(p_ao, p_wp, p_x1,
            CC, CC, CC, CC,
            ZERO, ZERO, ZERO, ZERO, ZERO, ZERO, 1,
            proj_b, x, 0, 0, nullptr, nullptr);
    }

    // 6) LN2 -> half
    ln_kernel<<<M, 256>>>(p_x1, ln2_g, ln2_b, p_ln);

    // 7) FC1 + GELU -> half
    {
        dim3 grid(DFF_ / 128, M / 128, 1);
        gemm_h<<<grid, 256>>>(p_ln, p_w1, p_h,
            CC, CC, CC, DFF_,
            ZERO, ZERO, ZERO, ZERO, ZERO, ZERO, 1,
            fc1_b, nullptr, 1, 1, nullptr, nullptr);
    }

    // 8) FC2 + residual -> out_x (fp32)
    {
        dim3 grid(CC / 128, M / 128, 1);
        gemm_h<<<grid, 256>>>(p_h, p_w2, out_x,
            DFF_, DFF_, DFF_, CC,
            ZERO, ZERO, ZERO, ZERO, ZERO, ZERO, 1,
            fc2_b, p_x1, 0, 0, nullptr, nullptr);
    }
}